// round 4
// baseline (speedup 1.0000x reference)
#include <cuda_runtime.h>
#include <math.h>

#define GD 60
#define GG 3600
#define NT 512

// shared memory layout (floats)
//   x_s   @ 0     : 32*96  = 3072
//   h_s   @ 3072  : 32*128 = 4096
//   hid_s @ 7168  : 32*192 = 6144
//   scr   @ 13312 : 6144
//   hwarp @ 19456 : 1024
//   fin   @ 20480 : 160
#define SMEM_FLOATS 20640
#define SMEM_BYTES (SMEM_FLOATS * 4)

struct Params {
    const float* mv;
    const float* boxes;
    const float* W_stats; const float* b_stats; const float* g_stats; const float* be_stats;
    const float* W_b1;    const float* b_b1;    const float* g_b1;    const float* be_b1;
    const float* W_b2;    const float* b_b2;    const float* g_b2;    const float* be_b2;
    const float* W_ih;    const float* W_hh;    const float* b_ih;    const float* b_hh;
    const float* W_p1;    const float* b_p1;    const float* W_p2;    const float* b_p2;
    const float* W_s1;    const float* b_s1;    const float* W_s2;    const float* b_s2;
    const float* W_c1;    const float* b_c1;    const float* W_c2;    const float* b_c2;
    float* out;
};

__device__ __forceinline__ float sig_(float x) {
    return __fdividef(1.0f, 1.0f + __expf(-x));
}
__device__ __forceinline__ float tanh_(float x) {
    return fmaf(2.0f, sig_(2.0f * x), -1.0f);
}

union F4 { float4 f; unsigned long long u2[2]; };

__device__ __forceinline__ void ffma2(unsigned long long& d,
                                      const unsigned long long a,
                                      const unsigned long long b) {
    asm("fma.rn.f32x2 %0, %1, %2, %0;" : "+l"(d) : "l"(a), "l"(b));
}
__device__ __forceinline__ float red2(unsigned long long v) {
    float lo, hi;
    asm("mov.b64 {%0, %1}, %2;" : "=f"(lo), "=f"(hi) : "l"(v));
    return lo + hi;
}
__device__ __forceinline__ void barq(int id) {
    asm volatile("bar.sync %0, 128;" :: "r"(id) : "memory");
}

__global__ void __launch_bounds__(NT, 1)
tracker_fused_kernel(Params p) {
    extern __shared__ float smem[];
    float* x_s   = smem;             // [32][96]
    float* h_s   = smem + 3072;      // [32][128]
    float* hid_s = smem + 7168;      // [32][192]
    float* scr   = smem + 13312;     // 6144
    float* hwarp = smem + 19456;     // [32][32]
    float* fin_s = smem + 20480;     // 160

    const int tid  = threadIdx.x;
    const int lane = tid & 31;
    const int w    = tid >> 5;       // 0..15
    const int quad = w >> 2;         // 0..3 (4-warp pipeline group)
    const int box0 = blockIdx.x * 32;

    // ================= Phase A: warp-local, boxes 2w, 2w+1 =================
    for (int bb = 0; bb < 2; bb++) {
        int b = 2 * w + bb;
        float4 bxr = __ldg((const float4*)p.boxes + (box0 + b));
        float bn0 = fminf(fmaxf(bxr.x * (1.0f / 960.0f), 0.0f), 1.0f);
        float bn1 = fminf(fmaxf(bxr.y * (1.0f / 960.0f), 0.0f), 1.0f);
        float bn2 = fminf(fmaxf(bxr.z * (1.0f / 960.0f), 0.0f), 1.0f);
        float bn3 = fminf(fmaxf(bxr.w * (1.0f / 960.0f), 0.0f), 1.0f);

        // --- rect motion stats ---
        int x1 = min(max((int)floorf(bn0 * 60.0f), 0), GD - 1);
        int y1 = min(max((int)floorf(bn1 * 60.0f), 0), GD - 1);
        int x2 = (int)ceilf(bn2 * 60.0f);
        int y2 = (int)ceilf(bn3 * 60.0f);
        x2 = min(max(x2, x1 + 1), GD);
        y2 = min(max(y2, y1 + 1), GD);
        int wd = x2 - x1;
        int area = wd * (y2 - y1);
        float s0 = 0.f, s1 = 0.f, q0 = 0.f, q1 = 0.f;
        float mx0 = -1e30f, mx1 = -1e30f, mn0 = 1e30f, mn1 = 1e30f;
        for (int c = lane; c < area; c += 32) {
            int ry = c / wd;
            int idx = (y1 + ry) * GD + x1 + (c - ry * wd);
            float v0 = __ldg(p.mv + idx);
            float v1 = __ldg(p.mv + GG + idx);
            s0 += v0; q0 += v0 * v0; mx0 = fmaxf(mx0, v0); mn0 = fminf(mn0, v0);
            s1 += v1; q1 += v1 * v1; mx1 = fmaxf(mx1, v1); mn1 = fminf(mn1, v1);
        }
        #pragma unroll
        for (int o = 16; o; o >>= 1) {
            s0 += __shfl_xor_sync(0xffffffffu, s0, o);
            s1 += __shfl_xor_sync(0xffffffffu, s1, o);
            q0 += __shfl_xor_sync(0xffffffffu, q0, o);
            q1 += __shfl_xor_sync(0xffffffffu, q1, o);
            mx0 = fmaxf(mx0, __shfl_xor_sync(0xffffffffu, mx0, o));
            mx1 = fmaxf(mx1, __shfl_xor_sync(0xffffffffu, mx1, o));
            mn0 = fminf(mn0, __shfl_xor_sync(0xffffffffu, mn0, o));
            mn1 = fminf(mn1, __shfl_xor_sync(0xffffffffu, mn1, o));
        }
        float rc = __fdividef(1.0f, (float)area);
        float m0 = s0 * rc, m1 = s1 * rc;
        float st[6];
        st[0] = m0;
        st[1] = m1;
        st[2] = sqrtf(fmaxf(q0 * rc - m0 * m0, 0.0f));
        st[3] = sqrtf(fmaxf(q1 * rc - m1 * m1, 0.0f));
        st[4] = mx0 - mn0;
        st[5] = mx1 - mn1;

        // --- z_mv: cols lane, lane+32 ---
        float za = __ldg(p.b_stats + lane);
        float zb = __ldg(p.b_stats + lane + 32);
        const float* wsa = p.W_stats + lane * 6;
        const float* wsb = p.W_stats + (lane + 32) * 6;
        #pragma unroll
        for (int k = 0; k < 6; k++) {
            za = fmaf(st[k], __ldg(wsa + k), za);
            zb = fmaf(st[k], __ldg(wsb + k), zb);
        }
        {
            float s = za + zb, q = za * za + zb * zb;
            #pragma unroll
            for (int o = 16; o; o >>= 1) {
                s += __shfl_xor_sync(0xffffffffu, s, o);
                q += __shfl_xor_sync(0xffffffffu, q, o);
            }
            float mu = s * (1.0f / 64.0f);
            float var = fmaxf(q * (1.0f / 64.0f) - mu * mu, 0.0f);
            float inv = rsqrtf(var + 1e-5f);
            x_s[b * 96 + lane] =
                fmaxf(fmaf((za - mu) * inv, __ldg(p.g_stats + lane), __ldg(p.be_stats + lane)), 0.0f);
            x_s[b * 96 + 32 + lane] =
                fmaxf(fmaf((zb - mu) * inv, __ldg(p.g_stats + lane + 32), __ldg(p.be_stats + lane + 32)), 0.0f);
        }

        // --- box path: 4 -> 32 LN relu -> 32 LN relu ---
        float t = __ldg(p.b_b1 + lane);
        const float* wb1 = p.W_b1 + lane * 4;
        t = fmaf(bn0, __ldg(wb1 + 0), t);
        t = fmaf(bn1, __ldg(wb1 + 1), t);
        t = fmaf(bn2, __ldg(wb1 + 2), t);
        t = fmaf(bn3, __ldg(wb1 + 3), t);
        {
            float s = t, q = t * t;
            #pragma unroll
            for (int o = 16; o; o >>= 1) {
                s += __shfl_xor_sync(0xffffffffu, s, o);
                q += __shfl_xor_sync(0xffffffffu, q, o);
            }
            float mu = s * (1.0f / 32.0f);
            float var = fmaxf(q * (1.0f / 32.0f) - mu * mu, 0.0f);
            float inv = rsqrtf(var + 1e-5f);
            hwarp[b * 32 + lane] =
                fmaxf(fmaf((t - mu) * inv, __ldg(p.g_b1 + lane), __ldg(p.be_b1 + lane)), 0.0f);
        }
        __syncwarp();
        float ta = __ldg(p.b_b2 + lane), tb = 0.0f;
        const float* wb2 = p.W_b2 + lane * 32;
        #pragma unroll
        for (int k4 = 0; k4 < 8; k4 += 2) {
            float4 wva = __ldg((const float4*)wb2 + k4);
            float4 wvb = __ldg((const float4*)wb2 + k4 + 1);
            const float* hp = hwarp + b * 32 + 4 * k4;
            ta = fmaf(hp[0], wva.x, ta);
            ta = fmaf(hp[1], wva.y, ta);
            ta = fmaf(hp[2], wva.z, ta);
            ta = fmaf(hp[3], wva.w, ta);
            tb = fmaf(hp[4], wvb.x, tb);
            tb = fmaf(hp[5], wvb.y, tb);
            tb = fmaf(hp[6], wvb.z, tb);
            tb = fmaf(hp[7], wvb.w, tb);
        }
        __syncwarp();
        {
            float t2 = ta + tb;
            float s = t2, q = t2 * t2;
            #pragma unroll
            for (int o = 16; o; o >>= 1) {
                s += __shfl_xor_sync(0xffffffffu, s, o);
                q += __shfl_xor_sync(0xffffffffu, q, o);
            }
            float mu = s * (1.0f / 32.0f);
            float var = fmaxf(q * (1.0f / 32.0f) - mu * mu, 0.0f);
            float inv = rsqrtf(var + 1e-5f);
            x_s[b * 96 + 64 + lane] =
                fmaxf(fmaf((t2 - mu) * inv, __ldg(p.g_b2 + lane), __ldg(p.be_b2 + lane)), 0.0f);
        }
    }

    barq(1 + quad);   // quad's x_s rows complete

    // ================= Gates GEMM (quad-local; weights via __ldg) =================
    // cg = w&3, bg = quad. Thread: hidden unit hu = lane+32*cg, i/g/o for boxes 8bg..+7.
    const int cg = w & 3;
    const int hu = lane + 32 * cg;

    unsigned long long acc[8][3];
    #pragma unroll
    for (int m = 0; m < 8; m++)
        #pragma unroll
        for (int u = 0; u < 3; u++) acc[m][u] = 0ull;

    {
        const float4* wp0 = (const float4*)(p.W_ih + hu * 96);          // i
        const float4* wp1 = (const float4*)(p.W_ih + (256 + hu) * 96);  // g
        const float4* wp2 = (const float4*)(p.W_ih + (384 + hu) * 96);  // o
        const float* xb = x_s + (8 * quad) * 96;

        #pragma unroll 6
        for (int k4 = 0; k4 < 24; k4++) {
            F4 wv0, wv1, wv2;
            wv0.f = __ldg(wp0 + k4);
            wv1.f = __ldg(wp1 + k4);
            wv2.f = __ldg(wp2 + k4);
            #pragma unroll
            for (int m = 0; m < 8; m++) {
                F4 xv;
                xv.f = *(const float4*)(xb + m * 96 + 4 * k4);
                ffma2(acc[m][0], xv.u2[0], wv0.u2[0]);
                ffma2(acc[m][0], xv.u2[1], wv0.u2[1]);
                ffma2(acc[m][1], xv.u2[0], wv1.u2[0]);
                ffma2(acc[m][1], xv.u2[1], wv1.u2[1]);
                ffma2(acc[m][2], xv.u2[0], wv2.u2[0]);
                ffma2(acc[m][2], xv.u2[1], wv2.u2[1]);
            }
        }
    }

    float bi  = __ldg(p.b_ih + hu)       + __ldg(p.b_hh + hu);
    float bgv = __ldg(p.b_ih + 256 + hu) + __ldg(p.b_hh + 256 + hu);
    float bo  = __ldg(p.b_ih + 384 + hu) + __ldg(p.b_hh + 384 + hu);

    // ================= LSTM (register-resident, h0=c0=0) =================
    #pragma unroll
    for (int m = 0; m < 8; m++) {
        float iv = red2(acc[m][0]) + bi;
        float gv = red2(acc[m][1]) + bgv;
        float ov = red2(acc[m][2]) + bo;
        float c = sig_(iv) * tanh_(gv);
        h_s[(8 * quad + m) * 128 + hu] = sig_(ov) * tanh_(c);
    }

    barq(1 + quad);   // quad's h_s rows complete

    // ================= Heads GEMM (quad-local, k-split in half) =================
    // cg2 = w&1 (col triple group), kh = (w>>1)&1 (k half), bg2 = quad
    const int cg2 = w & 1;
    const int kh  = (w >> 1) & 1;

    unsigned long long acc2[8][3];
    #pragma unroll
    for (int m = 0; m < 8; m++)
        #pragma unroll
        for (int u = 0; u < 3; u++) acc2[m][u] = 0ull;

    int ncol[3];
    const float4* wph[3];
    #pragma unroll
    for (int u = 0; u < 3; u++) {
        int n = lane + 32 * (3 * cg2 + u);
        ncol[u] = n;
        const float* src = (n < 64) ? (p.W_p1 + n * 128)
                         : (n < 128) ? (p.W_s1 + (n - 64) * 128)
                                     : (p.W_c1 + (n - 128) * 128);
        wph[u] = (const float4*)src;
    }

    {
        const float* hb = h_s + (8 * quad) * 128;
        const int k40 = kh * 16;
        #pragma unroll 4
        for (int kk = 0; kk < 16; kk++) {
            int k4 = k40 + kk;
            F4 wv0, wv1, wv2;
            wv0.f = __ldg(wph[0] + k4);
            wv1.f = __ldg(wph[1] + k4);
            wv2.f = __ldg(wph[2] + k4);
            #pragma unroll
            for (int m = 0; m < 8; m++) {
                F4 hv;
                hv.f = *(const float4*)(hb + m * 128 + 4 * k4);
                ffma2(acc2[m][0], hv.u2[0], wv0.u2[0]);
                ffma2(acc2[m][0], hv.u2[1], wv0.u2[1]);
                ffma2(acc2[m][1], hv.u2[0], wv1.u2[0]);
                ffma2(acc2[m][1], hv.u2[1], wv1.u2[1]);
                ffma2(acc2[m][2], hv.u2[0], wv2.u2[0]);
                ffma2(acc2[m][2], hv.u2[1], wv2.u2[1]);
            }
        }
    }

    float ar[8][3];
    #pragma unroll
    for (int m = 0; m < 8; m++)
        #pragma unroll
        for (int u = 0; u < 3; u++) ar[m][u] = red2(acc2[m][u]);

    float* sq = scr + quad * 1536 + (cg2 * 32 + lane) * 24;
    if (kh == 1) {
        #pragma unroll
        for (int m = 0; m < 8; m++)
            #pragma unroll
            for (int u = 0; u < 3; u++) sq[m * 3 + u] = ar[m][u];
    }
    barq(1 + quad);
    if (kh == 0) {
        #pragma unroll
        for (int u = 0; u < 3; u++) {
            int n = ncol[u];
            float bias = (n < 64) ? __ldg(p.b_p1 + n)
                       : (n < 128) ? __ldg(p.b_s1 + n - 64)
                                   : __ldg(p.b_c1 + n - 128);
            #pragma unroll
            for (int m = 0; m < 8; m++)
                hid_s[(8 * quad + m) * 192 + n] =
                    fmaxf(ar[m][u] + sq[m * 3 + u] + bias, 0.0f);
        }
    }
    __syncthreads();

    // ================= Head second layers (5 scalars per box) =================
    if (tid < 160) {
        int b = tid / 5, o = tid % 5;
        const float* hp = hid_s + b * 192 + ((o < 2) ? 0 : (o < 4) ? 64 : 128);
        const float* wp;
        float a;
        if (o == 0)      { wp = p.W_p2;      a = __ldg(p.b_p2); }
        else if (o == 1) { wp = p.W_p2 + 64; a = __ldg(p.b_p2 + 1); }
        else if (o == 2) { wp = p.W_s2;      a = __ldg(p.b_s2); }
        else if (o == 3) { wp = p.W_s2 + 64; a = __ldg(p.b_s2 + 1); }
        else             { wp = p.W_c2;      a = __ldg(p.b_c2); }
        #pragma unroll
        for (int k4 = 0; k4 < 16; k4++) {
            float4 hv = *(const float4*)(hp + 4 * k4);
            float4 wv = __ldg((const float4*)wp + k4);
            a = fmaf(hv.x, wv.x, a);
            a = fmaf(hv.y, wv.y, a);
            a = fmaf(hv.z, wv.z, a);
            a = fmaf(hv.w, wv.w, a);
        }
        fin_s[b * 5 + o] = a;
    }
    __syncthreads();

    // ================= Decode + output =================
    if (tid < 32) {
        int b = tid;
        float4 bx = __ldg((const float4*)p.boxes + (box0 + b));
        float cx = (bx.x + bx.z) * 0.5f, cy = (bx.y + bx.w) * 0.5f;
        float wd = bx.z - bx.x, hg = bx.w - bx.y;
        float ncx = cx + fin_s[b * 5 + 0];
        float ncy = cy + fin_s[b * 5 + 1];
        float nw = wd * __expf(fin_s[b * 5 + 2]);
        float nh = hg * __expf(fin_s[b * 5 + 3]);
        float conf = sig_(fin_s[b * 5 + 4]);
        float* op = p.out + (box0 + b) * 5;
        op[0] = ncx - nw * 0.5f;
        op[1] = ncy - nh * 0.5f;
        op[2] = ncx + nw * 0.5f;
        op[3] = ncy + nh * 0.5f;
        op[4] = conf;
    }
}

extern "C" void kernel_launch(void* const* d_in, const int* in_sizes, int n_in,
                              void* d_out, int out_size) {
    (void)in_sizes; (void)n_in; (void)out_size;
    Params p;
    p.mv       = (const float*)d_in[0];
    p.boxes    = (const float*)d_in[1];
    p.W_stats  = (const float*)d_in[2];
    p.b_stats  = (const float*)d_in[3];
    p.g_stats  = (const float*)d_in[4];
    p.be_stats = (const float*)d_in[5];
    p.W_b1     = (const float*)d_in[6];
    p.b_b1     = (const float*)d_in[7];
    p.g_b1     = (const float*)d_in[8];
    p.be_b1    = (const float*)d_in[9];
    p.W_b2     = (const float*)d_in[10];
    p.b_b2     = (const float*)d_in[11];
    p.g_b2     = (const float*)d_in[12];
    p.be_b2    = (const float*)d_in[13];
    p.W_ih     = (const float*)d_in[14];
    p.W_hh     = (const float*)d_in[15];
    p.b_ih     = (const float*)d_in[16];
    p.b_hh     = (const float*)d_in[17];
    p.W_p1     = (const float*)d_in[18];
    p.b_p1     = (const float*)d_in[19];
    p.W_p2     = (const float*)d_in[20];
    p.b_p2     = (const float*)d_in[21];
    p.W_s1     = (const float*)d_in[22];
    p.b_s1     = (const float*)d_in[23];
    p.W_s2     = (const float*)d_in[24];
    p.b_s2     = (const float*)d_in[25];
    p.W_c1     = (const float*)d_in[26];
    p.b_c1     = (const float*)d_in[27];
    p.W_c2     = (const float*)d_in[28];
    p.b_c2     = (const float*)d_in[29];
    p.out      = (float*)d_out;

    cudaFuncSetAttribute(tracker_fused_kernel,
                         cudaFuncAttributeMaxDynamicSharedMemorySize, SMEM_BYTES);
    tracker_fused_kernel<<<128, NT, SMEM_BYTES>>>(p);
}

// round 5
// speedup vs baseline: 1.8174x; 1.8174x over previous
#include <cuda_runtime.h>
#include <math.h>

#define GD 60
#define GG 3600
#define NT 512

// shared memory layout (floats)
//   x_s  @ 0      : 32*96  = 3072
//   wbuf @ 3072   : 38400  (gates tile 384*100 ; heads tile 192*132 ; scratch @ +25600 : 6144)
//   big  @ 41472  : 10400
#define XS_OFF  0
#define WB_OFF  3072
#define BIG_OFF 41472
#define SCR_OFF (WB_OFF + 25600)
#define SMEM_BYTES (51872 * 4)

struct Params {
    const float* mv;
    const float* boxes;
    const float* W_stats; const float* b_stats; const float* g_stats; const float* be_stats;
    const float* W_b1;    const float* b_b1;    const float* g_b1;    const float* be_b1;
    const float* W_b2;    const float* b_b2;    const float* g_b2;    const float* be_b2;
    const float* W_ih;    const float* W_hh;    const float* b_ih;    const float* b_hh;
    const float* W_p1;    const float* b_p1;    const float* W_p2;    const float* b_p2;
    const float* W_s1;    const float* b_s1;    const float* W_s2;    const float* b_s2;
    const float* W_c1;    const float* b_c1;    const float* W_c2;    const float* b_c2;
    float* out;
};

__device__ __forceinline__ float tanhfast(float x) {
    float y;
    asm("tanh.approx.f32 %0, %1;" : "=f"(y) : "f"(x));
    return y;
}
__device__ __forceinline__ float sigfast(float x) {
    return fmaf(0.5f, tanhfast(0.5f * x), 0.5f);
}

union F4 { float4 f; unsigned long long u2[2]; };

__device__ __forceinline__ void ffma2(unsigned long long& d,
                                      const unsigned long long a,
                                      const unsigned long long b) {
    asm("fma.rn.f32x2 %0, %1, %2, %0;" : "+l"(d) : "l"(a), "l"(b));
}
__device__ __forceinline__ float red2(unsigned long long v) {
    float lo, hi;
    asm("mov.b64 {%0, %1}, %2;" : "=f"(lo), "=f"(hi) : "l"(v));
    return lo + hi;
}

__device__ __forceinline__ void cp16(float* dst, const float* src) {
    unsigned saddr = (unsigned)__cvta_generic_to_shared(dst);
    asm volatile("cp.async.cg.shared.global [%0], [%1], 16;" :: "r"(saddr), "l"(src));
}

__global__ void __launch_bounds__(NT, 1)
tracker_fused_kernel(Params p) {
    extern __shared__ float smem[];
    float* x_s   = smem + XS_OFF;    // [32][96]
    float* wbuf  = smem + WB_OFF;
    float* big   = smem + BIG_OFF;
    float* scr   = smem + SCR_OFF;   // 6144 floats

    float* hwarp = big;              // phase A: [32][32]
    float* h_s   = big;              // phase B: [32][128]
    float* hid_s = big + 4096;       // [32][192]
    float* fin_s = big + 10240;      // 160

    const int tid  = threadIdx.x;
    const int lane = tid & 31;
    const int w    = tid >> 5;       // 0..15
    const int box0 = blockIdx.x * 32;

    // ============ Prefetch W_ih tile (f-gate skipped) ============
    #pragma unroll
    for (int it = 0; it < 18; it++) {
        int idx = tid + it * NT;
        int n = idx / 24, k4 = idx % 24;
        int row = (n < 128) ? n : n + 128;
        cp16(wbuf + n * 100 + 4 * k4, p.W_ih + row * 96 + 4 * k4);
    }
    asm volatile("cp.async.commit_group;");

    // ============ Phase A: both boxes (2w, 2w+1) interleaved ============
    {
        const int b0 = 2 * w, b1 = 2 * w + 1;

        // hoisted per-lane weight loads (off the dependent chain)
        const float* wsaP = p.W_stats + lane * 6;
        const float* wsbP = p.W_stats + (lane + 32) * 6;
        float ws_a[6], ws_b[6];
        #pragma unroll
        for (int k = 0; k < 6; k++) { ws_a[k] = __ldg(wsaP + k); ws_b[k] = __ldg(wsbP + k); }
        float bs_a  = __ldg(p.b_stats + lane),  bs_b  = __ldg(p.b_stats + lane + 32);
        float gs_a  = __ldg(p.g_stats + lane),  gs_b  = __ldg(p.g_stats + lane + 32);
        float bes_a = __ldg(p.be_stats + lane), bes_b = __ldg(p.be_stats + lane + 32);
        float4 wb1v = __ldg((const float4*)(p.W_b1) + lane);
        float bb1 = __ldg(p.b_b1 + lane), gb1 = __ldg(p.g_b1 + lane), beb1 = __ldg(p.be_b1 + lane);
        float bb2 = __ldg(p.b_b2 + lane), gb2 = __ldg(p.g_b2 + lane), beb2 = __ldg(p.be_b2 + lane);

        float4 bxA = __ldg((const float4*)p.boxes + (box0 + b0));
        float4 bxB = __ldg((const float4*)p.boxes + (box0 + b1));
        float anA0 = fminf(fmaxf(bxA.x * (1.0f / 960.0f), 0.0f), 1.0f);
        float anA1 = fminf(fmaxf(bxA.y * (1.0f / 960.0f), 0.0f), 1.0f);
        float anA2 = fminf(fmaxf(bxA.z * (1.0f / 960.0f), 0.0f), 1.0f);
        float anA3 = fminf(fmaxf(bxA.w * (1.0f / 960.0f), 0.0f), 1.0f);
        float anB0 = fminf(fmaxf(bxB.x * (1.0f / 960.0f), 0.0f), 1.0f);
        float anB1 = fminf(fmaxf(bxB.y * (1.0f / 960.0f), 0.0f), 1.0f);
        float anB2 = fminf(fmaxf(bxB.z * (1.0f / 960.0f), 0.0f), 1.0f);
        float anB3 = fminf(fmaxf(bxB.w * (1.0f / 960.0f), 0.0f), 1.0f);

        // rect bounds
        int xA1 = min(max((int)floorf(anA0 * 60.0f), 0), GD - 1);
        int yA1 = min(max((int)floorf(anA1 * 60.0f), 0), GD - 1);
        int xA2 = min(max((int)ceilf(anA2 * 60.0f), xA1 + 1), GD);
        int yA2 = min(max((int)ceilf(anA3 * 60.0f), yA1 + 1), GD);
        int xB1 = min(max((int)floorf(anB0 * 60.0f), 0), GD - 1);
        int yB1 = min(max((int)floorf(anB1 * 60.0f), 0), GD - 1);
        int xB2 = min(max((int)ceilf(anB2 * 60.0f), xB1 + 1), GD);
        int yB2 = min(max((int)ceilf(anB3 * 60.0f), yB1 + 1), GD);
        int wdA = xA2 - xA1, areaA = wdA * (yA2 - yA1);
        int wdB = xB2 - xB1, areaB = wdB * (yB2 - yB1);
        int maxArea = max(areaA, areaB);

        float sA0 = 0.f, sA1 = 0.f, qA0 = 0.f, qA1 = 0.f;
        float mxA0 = -1e30f, mxA1 = -1e30f, mnA0 = 1e30f, mnA1 = 1e30f;
        float sB0 = 0.f, sB1 = 0.f, qB0 = 0.f, qB1 = 0.f;
        float mxB0 = -1e30f, mxB1 = -1e30f, mnB0 = 1e30f, mnB1 = 1e30f;

        for (int c = lane; c < maxArea; c += 32) {
            if (c < areaA) {
                int ry = c / wdA;
                int idx = (yA1 + ry) * GD + xA1 + (c - ry * wdA);
                float v0 = __ldg(p.mv + idx);
                float v1 = __ldg(p.mv + GG + idx);
                sA0 += v0; qA0 += v0 * v0; mxA0 = fmaxf(mxA0, v0); mnA0 = fminf(mnA0, v0);
                sA1 += v1; qA1 += v1 * v1; mxA1 = fmaxf(mxA1, v1); mnA1 = fminf(mnA1, v1);
            }
            if (c < areaB) {
                int ry = c / wdB;
                int idx = (yB1 + ry) * GD + xB1 + (c - ry * wdB);
                float v0 = __ldg(p.mv + idx);
                float v1 = __ldg(p.mv + GG + idx);
                sB0 += v0; qB0 += v0 * v0; mxB0 = fmaxf(mxB0, v0); mnB0 = fminf(mnB0, v0);
                sB1 += v1; qB1 += v1 * v1; mxB1 = fmaxf(mxB1, v1); mnB1 = fminf(mnB1, v1);
            }
        }
        #pragma unroll
        for (int o = 16; o; o >>= 1) {
            sA0 += __shfl_xor_sync(0xffffffffu, sA0, o);
            sA1 += __shfl_xor_sync(0xffffffffu, sA1, o);
            qA0 += __shfl_xor_sync(0xffffffffu, qA0, o);
            qA1 += __shfl_xor_sync(0xffffffffu, qA1, o);
            sB0 += __shfl_xor_sync(0xffffffffu, sB0, o);
            sB1 += __shfl_xor_sync(0xffffffffu, sB1, o);
            qB0 += __shfl_xor_sync(0xffffffffu, qB0, o);
            qB1 += __shfl_xor_sync(0xffffffffu, qB1, o);
            mxA0 = fmaxf(mxA0, __shfl_xor_sync(0xffffffffu, mxA0, o));
            mxA1 = fmaxf(mxA1, __shfl_xor_sync(0xffffffffu, mxA1, o));
            mnA0 = fminf(mnA0, __shfl_xor_sync(0xffffffffu, mnA0, o));
            mnA1 = fminf(mnA1, __shfl_xor_sync(0xffffffffu, mnA1, o));
            mxB0 = fmaxf(mxB0, __shfl_xor_sync(0xffffffffu, mxB0, o));
            mxB1 = fmaxf(mxB1, __shfl_xor_sync(0xffffffffu, mxB1, o));
            mnB0 = fminf(mnB0, __shfl_xor_sync(0xffffffffu, mnB0, o));
            mnB1 = fminf(mnB1, __shfl_xor_sync(0xffffffffu, mnB1, o));
        }
        float rcA = __fdividef(1.0f, (float)areaA);
        float rcB = __fdividef(1.0f, (float)areaB);
        float mA0 = sA0 * rcA, mA1 = sA1 * rcA;
        float mB0 = sB0 * rcB, mB1 = sB1 * rcB;
        float stA[6], stB[6];
        stA[0] = mA0; stA[1] = mA1;
        stA[2] = sqrtf(fmaxf(qA0 * rcA - mA0 * mA0, 0.0f));
        stA[3] = sqrtf(fmaxf(qA1 * rcA - mA1 * mA1, 0.0f));
        stA[4] = mxA0 - mnA0; stA[5] = mxA1 - mnA1;
        stB[0] = mB0; stB[1] = mB1;
        stB[2] = sqrtf(fmaxf(qB0 * rcB - mB0 * mB0, 0.0f));
        stB[3] = sqrtf(fmaxf(qB1 * rcB - mB1 * mB1, 0.0f));
        stB[4] = mxB0 - mnB0; stB[5] = mxB1 - mnB1;

        // z_mv for both boxes (cols lane, lane+32)
        float zAa = bs_a, zAb = bs_b, zBa = bs_a, zBb = bs_b;
        #pragma unroll
        for (int k = 0; k < 6; k++) {
            zAa = fmaf(stA[k], ws_a[k], zAa);
            zAb = fmaf(stA[k], ws_b[k], zAb);
            zBa = fmaf(stB[k], ws_a[k], zBa);
            zBb = fmaf(stB[k], ws_b[k], zBb);
        }
        // LN64 both boxes
        {
            float sA = zAa + zAb, qA = zAa * zAa + zAb * zAb;
            float sB = zBa + zBb, qB = zBa * zBa + zBb * zBb;
            #pragma unroll
            for (int o = 16; o; o >>= 1) {
                sA += __shfl_xor_sync(0xffffffffu, sA, o);
                qA += __shfl_xor_sync(0xffffffffu, qA, o);
                sB += __shfl_xor_sync(0xffffffffu, sB, o);
                qB += __shfl_xor_sync(0xffffffffu, qB, o);
            }
            float muA = sA * (1.0f / 64.0f);
            float invA = rsqrtf(fmaxf(qA * (1.0f / 64.0f) - muA * muA, 0.0f) + 1e-5f);
            float muB = sB * (1.0f / 64.0f);
            float invB = rsqrtf(fmaxf(qB * (1.0f / 64.0f) - muB * muB, 0.0f) + 1e-5f);
            x_s[b0 * 96 + lane]      = fmaxf(fmaf((zAa - muA) * invA, gs_a, bes_a), 0.0f);
            x_s[b0 * 96 + 32 + lane] = fmaxf(fmaf((zAb - muA) * invA, gs_b, bes_b), 0.0f);
            x_s[b1 * 96 + lane]      = fmaxf(fmaf((zBa - muB) * invB, gs_a, bes_a), 0.0f);
            x_s[b1 * 96 + 32 + lane] = fmaxf(fmaf((zBb - muB) * invB, gs_b, bes_b), 0.0f);
        }

        // box path layer 1 (both boxes)
        float tA = bb1, tB = bb1;
        tA = fmaf(anA0, wb1v.x, tA); tB = fmaf(anB0, wb1v.x, tB);
        tA = fmaf(anA1, wb1v.y, tA); tB = fmaf(anB1, wb1v.y, tB);
        tA = fmaf(anA2, wb1v.z, tA); tB = fmaf(anB2, wb1v.z, tB);
        tA = fmaf(anA3, wb1v.w, tA); tB = fmaf(anB3, wb1v.w, tB);
        {
            float sA = tA, qA = tA * tA, sB = tB, qB = tB * tB;
            #pragma unroll
            for (int o = 16; o; o >>= 1) {
                sA += __shfl_xor_sync(0xffffffffu, sA, o);
                qA += __shfl_xor_sync(0xffffffffu, qA, o);
                sB += __shfl_xor_sync(0xffffffffu, sB, o);
                qB += __shfl_xor_sync(0xffffffffu, qB, o);
            }
            float muA = sA * (1.0f / 32.0f);
            float invA = rsqrtf(fmaxf(qA * (1.0f / 32.0f) - muA * muA, 0.0f) + 1e-5f);
            float muB = sB * (1.0f / 32.0f);
            float invB = rsqrtf(fmaxf(qB * (1.0f / 32.0f) - muB * muB, 0.0f) + 1e-5f);
            hwarp[b0 * 32 + lane] = fmaxf(fmaf((tA - muA) * invA, gb1, beb1), 0.0f);
            hwarp[b1 * 32 + lane] = fmaxf(fmaf((tB - muB) * invB, gb1, beb1), 0.0f);
        }
        __syncwarp();
        // box path layer 2 (both boxes), split accumulators
        float tA0 = bb2, tA1 = 0.0f, tB0 = bb2, tB1 = 0.0f;
        const float* wb2 = p.W_b2 + lane * 32;
        #pragma unroll
        for (int k4 = 0; k4 < 8; k4 += 2) {
            float4 wva = __ldg((const float4*)wb2 + k4);
            float4 wvb = __ldg((const float4*)wb2 + k4 + 1);
            const float* hpA = hwarp + b0 * 32 + 4 * k4;
            const float* hpB = hwarp + b1 * 32 + 4 * k4;
            tA0 = fmaf(hpA[0], wva.x, tA0); tB0 = fmaf(hpB[0], wva.x, tB0);
            tA0 = fmaf(hpA[1], wva.y, tA0); tB0 = fmaf(hpB[1], wva.y, tB0);
            tA0 = fmaf(hpA[2], wva.z, tA0); tB0 = fmaf(hpB[2], wva.z, tB0);
            tA0 = fmaf(hpA[3], wva.w, tA0); tB0 = fmaf(hpB[3], wva.w, tB0);
            tA1 = fmaf(hpA[4], wvb.x, tA1); tB1 = fmaf(hpB[4], wvb.x, tB1);
            tA1 = fmaf(hpA[5], wvb.y, tA1); tB1 = fmaf(hpB[5], wvb.y, tB1);
            tA1 = fmaf(hpA[6], wvb.z, tA1); tB1 = fmaf(hpB[6], wvb.z, tB1);
            tA1 = fmaf(hpA[7], wvb.w, tA1); tB1 = fmaf(hpB[7], wvb.w, tB1);
        }
        __syncwarp();
        {
            float t2A = tA0 + tA1, t2B = tB0 + tB1;
            float sA = t2A, qA = t2A * t2A, sB = t2B, qB = t2B * t2B;
            #pragma unroll
            for (int o = 16; o; o >>= 1) {
                sA += __shfl_xor_sync(0xffffffffu, sA, o);
                qA += __shfl_xor_sync(0xffffffffu, qA, o);
                sB += __shfl_xor_sync(0xffffffffu, sB, o);
                qB += __shfl_xor_sync(0xffffffffu, qB, o);
            }
            float muA = sA * (1.0f / 32.0f);
            float invA = rsqrtf(fmaxf(qA * (1.0f / 32.0f) - muA * muA, 0.0f) + 1e-5f);
            float muB = sB * (1.0f / 32.0f);
            float invB = rsqrtf(fmaxf(qB * (1.0f / 32.0f) - muB * muB, 0.0f) + 1e-5f);
            x_s[b0 * 96 + 64 + lane] = fmaxf(fmaf((t2A - muA) * invA, gb2, beb2), 0.0f);
            x_s[b1 * 96 + 64 + lane] = fmaxf(fmaf((t2B - muB) * invB, gb2, beb2), 0.0f);
        }
    }

    asm volatile("cp.async.wait_group 0;");
    __syncthreads();   // x_s complete + W_ih staged

    // ============ Gates GEMM (f32x2, k-paired) ============
    const int cg = w & 3;
    const int bg = w >> 2;
    const int hu = lane + 32 * cg;

    unsigned long long acc[8][3];
    #pragma unroll
    for (int m = 0; m < 8; m++)
        #pragma unroll
        for (int u = 0; u < 3; u++) acc[m][u] = 0ull;

    {
        const int wr0 = hu * 100;
        const int wr1 = (hu + 128) * 100;
        const int wr2 = (hu + 256) * 100;
        const float* xb = x_s + (8 * bg) * 96;

        #pragma unroll 4
        for (int k4 = 0; k4 < 24; k4++) {
            F4 wv0, wv1, wv2;
            wv0.f = *(const float4*)(wbuf + wr0 + 4 * k4);
            wv1.f = *(const float4*)(wbuf + wr1 + 4 * k4);
            wv2.f = *(const float4*)(wbuf + wr2 + 4 * k4);
            #pragma unroll
            for (int m = 0; m < 8; m++) {
                F4 xv;
                xv.f = *(const float4*)(xb + m * 96 + 4 * k4);
                ffma2(acc[m][0], xv.u2[0], wv0.u2[0]);
                ffma2(acc[m][0], xv.u2[1], wv0.u2[1]);
                ffma2(acc[m][1], xv.u2[0], wv1.u2[0]);
                ffma2(acc[m][1], xv.u2[1], wv1.u2[1]);
                ffma2(acc[m][2], xv.u2[0], wv2.u2[0]);
                ffma2(acc[m][2], xv.u2[1], wv2.u2[1]);
            }
        }
    }

    float bi  = __ldg(p.b_ih + hu)       + __ldg(p.b_hh + hu);
    float bgv = __ldg(p.b_ih + 256 + hu) + __ldg(p.b_hh + 256 + hu);
    float bo  = __ldg(p.b_ih + 384 + hu) + __ldg(p.b_hh + 384 + hu);

    __syncthreads();   // all wbuf reads done before heads restage

    // ============ Prefetch heads weights ============
    #pragma unroll
    for (int it = 0; it < 12; it++) {
        int idx = tid + it * NT;
        int n = idx >> 5, k4 = idx & 31;
        const float* src = (n < 64) ? (p.W_p1 + n * 128)
                         : (n < 128) ? (p.W_s1 + (n - 64) * 128)
                                     : (p.W_c1 + (n - 128) * 128);
        cp16(wbuf + n * 132 + 4 * k4, src + 4 * k4);
    }
    asm volatile("cp.async.commit_group;");

    // ============ LSTM in registers (h0=c0=0, tanh.approx) ============
    #pragma unroll
    for (int m = 0; m < 8; m++) {
        float iv = red2(acc[m][0]) + bi;
        float gv = red2(acc[m][1]) + bgv;
        float ov = red2(acc[m][2]) + bo;
        float c = sigfast(iv) * tanhfast(gv);
        h_s[(8 * bg + m) * 128 + hu] = sigfast(ov) * tanhfast(c);
    }

    asm volatile("cp.async.wait_group 0;");
    __syncthreads();   // h_s ready + heads weights staged

    // ============ Heads GEMM (f32x2, k-split across warp halves) ============
    const int kh  = w >> 3;
    const int cg2 = (w & 7) & 1;
    const int bg2 = (w & 7) >> 1;

    unsigned long long acc2[8][3];
    #pragma unroll
    for (int m = 0; m < 8; m++)
        #pragma unroll
        for (int u = 0; u < 3; u++) acc2[m][u] = 0ull;

    {
        int wr[3];
        #pragma unroll
        for (int u = 0; u < 3; u++) wr[u] = (lane + 32 * (3 * cg2 + u)) * 132;
        const float* hb = h_s + (8 * bg2) * 128;
        const int k40 = kh * 16;

        #pragma unroll 4
        for (int kk = 0; kk < 16; kk++) {
            int k4 = k40 + kk;
            F4 wv0, wv1, wv2;
            wv0.f = *(const float4*)(wbuf + wr[0] + 4 * k4);
            wv1.f = *(const float4*)(wbuf + wr[1] + 4 * k4);
            wv2.f = *(const float4*)(wbuf + wr[2] + 4 * k4);
            #pragma unroll
            for (int m = 0; m < 8; m++) {
                F4 hv;
                hv.f = *(const float4*)(hb + m * 128 + 4 * k4);
                ffma2(acc2[m][0], hv.u2[0], wv0.u2[0]);
                ffma2(acc2[m][0], hv.u2[1], wv0.u2[1]);
                ffma2(acc2[m][1], hv.u2[0], wv1.u2[0]);
                ffma2(acc2[m][1], hv.u2[1], wv1.u2[1]);
                ffma2(acc2[m][2], hv.u2[0], wv2.u2[0]);
                ffma2(acc2[m][2], hv.u2[1], wv2.u2[1]);
            }
        }
    }

    float ar[8][3];
    #pragma unroll
    for (int m = 0; m < 8; m++)
        #pragma unroll
        for (int u = 0; u < 3; u++) ar[m][u] = red2(acc2[m][u]);

    const int sbase = (((bg2 * 2 + cg2) * 32) + lane) * 24;
    if (kh == 1) {
        #pragma unroll
        for (int m = 0; m < 8; m++)
            #pragma unroll
            for (int u = 0; u < 3; u++) scr[sbase + m * 3 + u] = ar[m][u];
    }
    __syncthreads();
    if (kh == 0) {
        #pragma unroll
        for (int u = 0; u < 3; u++) {
            int n = lane + 32 * (3 * cg2 + u);
            float bias = (n < 64) ? __ldg(p.b_p1 + n)
                       : (n < 128) ? __ldg(p.b_s1 + n - 64)
                                   : __ldg(p.b_c1 + n - 128);
            #pragma unroll
            for (int m = 0; m < 8; m++)
                hid_s[(8 * bg2 + m) * 192 + n] =
                    fmaxf(ar[m][u] + scr[sbase + m * 3 + u] + bias, 0.0f);
        }
    }
    __syncthreads();

    // ============ Head second layers ============
    if (tid < 160) {
        int b = tid / 5, o = tid % 5;
        const float* hp = hid_s + b * 192 + ((o < 2) ? 0 : (o < 4) ? 64 : 128);
        const float* wp;
        float a;
        if (o == 0)      { wp = p.W_p2;      a = __ldg(p.b_p2); }
        else if (o == 1) { wp = p.W_p2 + 64; a = __ldg(p.b_p2 + 1); }
        else if (o == 2) { wp = p.W_s2;      a = __ldg(p.b_s2); }
        else if (o == 3) { wp = p.W_s2 + 64; a = __ldg(p.b_s2 + 1); }
        else             { wp = p.W_c2;      a = __ldg(p.b_c2); }
        #pragma unroll
        for (int k4 = 0; k4 < 16; k4++) {
            float4 hv = *(const float4*)(hp + 4 * k4);
            float4 wv = __ldg((const float4*)wp + k4);
            a = fmaf(hv.x, wv.x, a);
            a = fmaf(hv.y, wv.y, a);
            a = fmaf(hv.z, wv.z, a);
            a = fmaf(hv.w, wv.w, a);
        }
        fin_s[b * 5 + o] = a;
    }
    __syncthreads();

    // ============ Decode + output ============
    if (tid < 32) {
        int b = tid;
        float4 bx = __ldg((const float4*)p.boxes + (box0 + b));
        float cx = (bx.x + bx.z) * 0.5f, cy = (bx.y + bx.w) * 0.5f;
        float wd = bx.z - bx.x, hg = bx.w - bx.y;
        float ncx = cx + fin_s[b * 5 + 0];
        float ncy = cy + fin_s[b * 5 + 1];
        float nw = wd * __expf(fin_s[b * 5 + 2]);
        float nh = hg * __expf(fin_s[b * 5 + 3]);
        float conf = __fdividef(1.0f, 1.0f + __expf(-fin_s[b * 5 + 4]));
        float* op = p.out + (box0 + b) * 5;
        op[0] = ncx - nw * 0.5f;
        op[1] = ncy - nh * 0.5f;
        op[2] = ncx + nw * 0.5f;
        op[3] = ncy + nh * 0.5f;
        op[4] = conf;
    }
}

extern "C" void kernel_launch(void* const* d_in, const int* in_sizes, int n_in,
                              void* d_out, int out_size) {
    (void)in_sizes; (void)n_in; (void)out_size;
    Params p;
    p.mv       = (const float*)d_in[0];
    p.boxes    = (const float*)d_in[1];
    p.W_stats  = (const float*)d_in[2];
    p.b_stats  = (const float*)d_in[3];
    p.g_stats  = (const float*)d_in[4];
    p.be_stats = (const float*)d_in[5];
    p.W_b1     = (const float*)d_in[6];
    p.b_b1     = (const float*)d_in[7];
    p.g_b1     = (const float*)d_in[8];
    p.be_b1    = (const float*)d_in[9];
    p.W_b2     = (const float*)d_in[10];
    p.b_b2     = (const float*)d_in[11];
    p.g_b2     = (const float*)d_in[12];
    p.be_b2    = (const float*)d_in[13];
    p.W_ih     = (const float*)d_in[14];
    p.W_hh     = (const float*)d_in[15];
    p.b_ih     = (const float*)d_in[16];
    p.b_hh     = (const float*)d_in[17];
    p.W_p1     = (const float*)d_in[18];
    p.b_p1     = (const float*)d_in[19];
    p.W_p2     = (const float*)d_in[20];
    p.b_p2     = (const float*)d_in[21];
    p.W_s1     = (const float*)d_in[22];
    p.b_s1     = (const float*)d_in[23];
    p.W_s2     = (const float*)d_in[24];
    p.b_s2     = (const float*)d_in[25];
    p.W_c1     = (const float*)d_in[26];
    p.b_c1     = (const float*)d_in[27];
    p.W_c2     = (const float*)d_in[28];
    p.b_c2     = (const float*)d_in[29];
    p.out      = (float*)d_out;

    cudaFuncSetAttribute(tracker_fused_kernel,
                         cudaFuncAttributeMaxDynamicSharedMemorySize, SMEM_BYTES);
    tracker_fused_kernel<<<128, NT, SMEM_BYTES>>>(p);
}